// round 10
// baseline (speedup 1.0000x reference)
#include <cuda_runtime.h>

#define HW_DIM 10
#define NUM_DEV 50
#define NUM_INT 101
#define ODIM 30
#define ROW (NUM_INT * ODIM)   // 3030 floats per expert

__shared__ __align__(16) float gs[4][16];   // per-warp gates
__shared__ float accsh[4][32];              // per-warp partial outputs
__shared__ float ssh[4];                    // per-warp partial softmax sums

// One warp's fully-unrolled, clamp-free work: experts [BASE, BASE+CNT).
template<int CNT, int BASE>
__device__ __forceinline__ void warp_work(
    int w, int lane, int idx, int d,
    const float* __restrict__ h,
    const float* __restrict__ hw_emb,
    const float* __restrict__ expert_emb)
{
    // Gate-row load: lanes 0..CNT-1 own experts BASE+lane (others dup lane 0)
    const int eg = BASE + ((lane < CNT) ? lane : 0);
    float he[HW_DIM];
    {
        const float2* p = (const float2*)(hw_emb + eg * HW_DIM);
#pragma unroll
        for (int j = 0; j < 5; ++j) { float2 t = __ldg(p + j); he[2*j] = t.x; he[2*j+1] = t.y; }
    }

    // Gather: CNT loads, addresses fully affine (no clamps, no SELs)
    const float* gbase = expert_emb + (size_t)BASE * ROW + (size_t)idx * ODIM + d;
    float v[CNT];
#pragma unroll
    for (int j = 0; j < CNT; ++j)
        v[j] = __ldg(gbase + (size_t)j * ROW);

    // Gate: one dot -> sin -> exp per lane (sin in [-1,1], no max-sub)
    const float inv_sqrt = 0.31622776601683794f;
    float dt0 = 0.f, dt1 = 0.f;
#pragma unroll
    for (int j = 0; j < 5; ++j) {
        dt0 = fmaf(h[2*j],   he[2*j],   dt0);
        dt1 = fmaf(h[2*j+1], he[2*j+1], dt1);
    }
    const float g = __expf(__sinf((dt0 + dt1) * inv_sqrt));

    if (lane < CNT) gs[w][lane] = g;           // single predicate, no pad writes
    __syncwarp();

    // Combine: vectorized gate reads, CNT FMAs, fused softmax partial sum
    float accA = 0.f, accB = 0.f, sA = 0.f, sB = 0.f;
#pragma unroll
    for (int i = 0; i < CNT / 4; ++i) {
        const float4 gq = *(const float4*)(gs[w] + 4 * i);
        accA = fmaf(gq.x, v[4*i+0], accA);  sA += gq.x;
        accB = fmaf(gq.y, v[4*i+1], accB);  sB += gq.y;
        accA = fmaf(gq.z, v[4*i+2], accA);  sA += gq.z;
        accB = fmaf(gq.w, v[4*i+3], accB);  sB += gq.w;
    }
#pragma unroll
    for (int j = (CNT / 4) * 4; j < CNT; ++j) {  // tail (1 for CNT=13, 0 for CNT=12)
        const float ga = gs[w][j];
        accA = fmaf(ga, v[j], accA);  sA += ga;
    }

    accsh[w][lane] = accA + accB;
    if (lane == 0) ssh[w] = sA + sB;
}

// 4 warps: experts 13+13+12+12 = 50, each warp's path compile-time exact.
__global__ __launch_bounds__(128, 1)
void mhn_kernel(const float* __restrict__ x,
                const float* __restrict__ hw,
                const float* __restrict__ hw_emb,
                const float* __restrict__ expert_emb,
                float* __restrict__ out)
{
    const int tid  = threadIdx.x;
    const int w    = tid >> 5;
    const int lane = tid & 31;

    // ---- Chain A root: x first; minimal idx chain ----
    const float xv  = __ldg(x);
    const int   idx = __float2int_rn(xv * (float)(NUM_INT - 1));

    // ---- hw broadcast load (in flight while x resolves) ----
    float h[HW_DIM];
    {
        const float4 h0 = __ldg((const float4*)hw);
        const float4 h1 = __ldg((const float4*)(hw + 4));
        const float2 h2 = __ldg((const float2*)(hw + 8));
        h[0]=h0.x; h[1]=h0.y; h[2]=h0.z; h[3]=h0.w;
        h[4]=h1.x; h[5]=h1.y; h[6]=h1.z; h[7]=h1.w;
        h[8]=h2.x; h[9]=h2.y;
    }

    const int d = (lane < ODIM) ? lane : 0;

    if      (w == 0) warp_work<13,  0>(0, lane, idx, d, h, hw_emb, expert_emb);
    else if (w == 1) warp_work<13, 13>(1, lane, idx, d, h, hw_emb, expert_emb);
    else if (w == 2) warp_work<12, 26>(2, lane, idx, d, h, hw_emb, expert_emb);
    else             warp_work<12, 38>(3, lane, idx, d, h, hw_emb, expert_emb);

    __syncthreads();

    // ---- Warp 0 merges 4 partials and writes ----
    if (tid < ODIM) {
        const float num = (accsh[0][tid] + accsh[1][tid])
                        + (accsh[2][tid] + accsh[3][tid]);
        const float den = (ssh[0] + ssh[1]) + (ssh[2] + ssh[3]);
        out[tid] = __fdividef(num, den);
    }
}

extern "C" void kernel_launch(void* const* d_in, const int* in_sizes, int n_in,
                              void* d_out, int out_size)
{
    const float* x          = (const float*)d_in[0];
    const float* hw         = (const float*)d_in[1];
    const float* hw_emb     = (const float*)d_in[2];
    const float* expert_emb = (const float*)d_in[3];
    float* out = (float*)d_out;

    mhn_kernel<<<1, 128>>>(x, hw, hw_emb, expert_emb, out);
}

// round 11
// speedup vs baseline: 1.3355x; 1.3355x over previous
#include <cuda_runtime.h>

#define HW_DIM 10
#define NUM_DEV 50
#define NUM_INT 101
#define ODIM 30
#define EPW 13                 // expert slots per warp (4*13=52, slots 50,51 padded)
#define ROW (NUM_INT * ODIM)   // 3030 floats per expert

// 4 warps, ~13 experts each. Slots >= 50 clamp address to expert 49 with a
// zero gate (contribute nothing). Per-warp: 13 gather LDGs, one gate per
// active lane, 13-FMA combine. One __syncthreads merge tail.
__global__ __launch_bounds__(128, 1)
void mhn_kernel(const float* __restrict__ x,
                const float* __restrict__ hw,
                const float* __restrict__ hw_emb,
                const float* __restrict__ expert_emb,
                float* __restrict__ out)
{
    const int tid  = threadIdx.x;
    const int w    = tid >> 5;
    const int lane = tid & 31;

    __shared__ __align__(16) float gs[4][16];  // per-warp gates (13 valid, rest 0)
    __shared__ float accsh[4][32];             // per-warp partial outputs
    __shared__ float ssh[4];                   // per-warp partial softmax sums

    // ---- Chain A root: x first; minimal idx chain ----
    const float xv  = __ldg(x);
    const int   idx = __float2int_rn(xv * (float)(NUM_INT - 1));

    // ---- Chain B loads (in flight while x resolves) ----
    float h[HW_DIM];
    {
        const float4 h0 = __ldg((const float4*)hw);
        const float4 h1 = __ldg((const float4*)(hw + 4));
        const float2 h2 = __ldg((const float2*)(hw + 8));
        h[0]=h0.x; h[1]=h0.y; h[2]=h0.z; h[3]=h0.w;
        h[4]=h1.x; h[5]=h1.y; h[6]=h1.z; h[7]=h1.w;
        h[8]=h2.x; h[9]=h2.y;
    }
    // Gate expert for this lane (only lanes < EPW with valid slot matter)
    const int slot = w * EPW + ((lane < EPW) ? lane : 0);
    const int eg   = (slot < NUM_DEV) ? slot : (NUM_DEV - 1);
    float he[HW_DIM];
    {
        const float2* p = (const float2*)(hw_emb + eg * HW_DIM);
#pragma unroll
        for (int j = 0; j < 5; ++j) { float2 t = __ldg(p + j); he[2*j] = t.x; he[2*j+1] = t.y; }
    }

    // ---- Chain A: 13 gather loads per warp (addresses clamped for pads) ----
    const int d = (lane < ODIM) ? lane : 0;
    float v[EPW];
#pragma unroll
    for (int j = 0; j < EPW; ++j) {
        int e = w * EPW + j;
        if (e >= NUM_DEV) e = NUM_DEV - 1;       // cheap SEL on pad slots only
        v[j] = __ldg(expert_emb + (size_t)e * ROW + (size_t)idx * ODIM + d);
    }

    // ---- Gate: one dot -> sin -> exp per lane ----
    const float inv_sqrt = 0.31622776601683794f;
    float dt0 = 0.f, dt1 = 0.f;
#pragma unroll
    for (int j = 0; j < 5; ++j) {
        dt0 = fmaf(h[2*j],   he[2*j],   dt0);
        dt1 = fmaf(h[2*j+1], he[2*j+1], dt1);
    }
    const float g = __expf(__sinf((dt0 + dt1) * inv_sqrt));

    // Publish gates: zero for pad slots and unused lanes (13..15)
    if (lane < 16) gs[w][lane] = (lane < EPW && slot < NUM_DEV) ? g : 0.f;
    __syncwarp();

    // ---- Per-warp combine: 3x float4 + 1 scalar gate reads, 13 FMAs ----
    const float4* g4 = (const float4*)gs[w];
    float accA = 0.f, accB = 0.f, sA = 0.f, sB = 0.f;
#pragma unroll
    for (int i = 0; i < 3; ++i) {
        const float4 gq = g4[i];
        accA = fmaf(gq.x, v[4*i+0], accA);  sA += gq.x;
        accB = fmaf(gq.y, v[4*i+1], accB);  sB += gq.y;
        accA = fmaf(gq.z, v[4*i+2], accA);  sA += gq.z;
        accB = fmaf(gq.w, v[4*i+3], accB);  sB += gq.w;
    }
    {   const float ga = gs[w][12];
        accA = fmaf(ga, v[12], accA);  sA += ga; }

    accsh[w][lane] = accA + accB;
    if (lane == 0) ssh[w] = sA + sB;
    __syncthreads();

    // ---- Warp 0 merges 4 partials and writes ----
    if (tid < ODIM) {
        const float num = (accsh[0][tid] + accsh[1][tid])
                        + (accsh[2][tid] + accsh[3][tid]);
        const float den = (ssh[0] + ssh[1]) + (ssh[2] + ssh[3]);
        out[tid] = __fdividef(num, den);
    }
}

extern "C" void kernel_launch(void* const* d_in, const int* in_sizes, int n_in,
                              void* d_out, int out_size)
{
    const float* x          = (const float*)d_in[0];
    const float* hw         = (const float*)d_in[1];
    const float* hw_emb     = (const float*)d_in[2];
    const float* expert_emb = (const float*)d_in[3];
    float* out = (float*)d_out;

    mhn_kernel<<<1, 128>>>(x, hw, hw_emb, expert_emb, out);
}

// round 12
// speedup vs baseline: 1.4476x; 1.0839x over previous
#include <cuda_runtime.h>

#define HW_DIM 10
#define NUM_DEV 50
#define NUM_INT 101
#define ODIM 30
#define EPW 13                 // expert slots per warp (4*13=52, slots 50,51 padded)
#define ROW (NUM_INT * ODIM)   // 3030 floats per expert

// 4 warps, 13 expert-slots each (slots >= 50: address clamped, gate forced 0).
// Per-warp: 13 gather LDGs, one gate per lane, combine via 13 register
// shuffles (no shared gate array, no __syncwarp). One __syncthreads merge.
__global__ __launch_bounds__(128, 1)
void mhn_kernel(const float* __restrict__ x,
                const float* __restrict__ hw,
                const float* __restrict__ hw_emb,
                const float* __restrict__ expert_emb,
                float* __restrict__ out)
{
    const int tid  = threadIdx.x;
    const int w    = tid >> 5;
    const int lane = tid & 31;
    const unsigned full = 0xffffffffu;

    __shared__ float accsh[4][32];   // per-warp partial outputs
    __shared__ float ssh[4];         // per-warp partial softmax sums

    // ---- Chain A root: x first; minimal idx chain ----
    const float xv  = __ldg(x);
    const int   idx = __float2int_rn(xv * (float)(NUM_INT - 1));

    // ---- Chain B loads (in flight while x resolves) ----
    float h[HW_DIM];
    {
        const float4 h0 = __ldg((const float4*)hw);
        const float4 h1 = __ldg((const float4*)(hw + 4));
        const float2 h2 = __ldg((const float2*)(hw + 8));
        h[0]=h0.x; h[1]=h0.y; h[2]=h0.z; h[3]=h0.w;
        h[4]=h1.x; h[5]=h1.y; h[6]=h1.z; h[7]=h1.w;
        h[8]=h2.x; h[9]=h2.y;
    }
    // Gate expert for this lane (lanes 0..12 own slots; pads clamp to 49)
    const int slot = w * EPW + ((lane < EPW) ? lane : 0);
    const int eg   = (slot < NUM_DEV) ? slot : (NUM_DEV - 1);
    float he[HW_DIM];
    {
        const float2* p = (const float2*)(hw_emb + eg * HW_DIM);
#pragma unroll
        for (int j = 0; j < 5; ++j) { float2 t = __ldg(p + j); he[2*j] = t.x; he[2*j+1] = t.y; }
    }

    // ---- Chain A: 13 gather loads per warp (addresses clamped for pads) ----
    const int d = (lane < ODIM) ? lane : 0;
    float v[EPW];
#pragma unroll
    for (int j = 0; j < EPW; ++j) {
        int e = w * EPW + j;
        if (e >= NUM_DEV) e = NUM_DEV - 1;       // SEL on pad slots only
        v[j] = __ldg(expert_emb + (size_t)e * ROW + (size_t)idx * ODIM + d);
    }

    // ---- Gate: one dot -> sin -> exp per lane; pad slots carry zero gate ----
    const float inv_sqrt = 0.31622776601683794f;
    float dt0 = 0.f, dt1 = 0.f;
#pragma unroll
    for (int j = 0; j < 5; ++j) {
        dt0 = fmaf(h[2*j],   he[2*j],   dt0);
        dt1 = fmaf(h[2*j+1], he[2*j+1], dt1);
    }
    const float g = (slot < NUM_DEV) ? __expf(__sinf((dt0 + dt1) * inv_sqrt)) : 0.f;

    // ---- Per-warp combine: gates via register shuffle (no shared, no barrier) ----
    float accA = 0.f, accB = 0.f, sA = 0.f, sB = 0.f;
#pragma unroll
    for (int j = 0; j < 12; j += 2) {
        const float ga = __shfl_sync(full, g, j);
        const float gb = __shfl_sync(full, g, j + 1);
        accA = fmaf(ga, v[j],     accA);  sA += ga;
        accB = fmaf(gb, v[j + 1], accB);  sB += gb;
    }
    {   const float gc = __shfl_sync(full, g, 12);
        accA = fmaf(gc, v[12], accA);  sA += gc; }

    accsh[w][lane] = accA + accB;
    if (lane == 0) ssh[w] = sA + sB;
    __syncthreads();

    // ---- Warp 0 merges 4 partials and writes ----
    if (tid < ODIM) {
        const float num = (accsh[0][tid] + accsh[1][tid])
                        + (accsh[2][tid] + accsh[3][tid]);
        const float den = (ssh[0] + ssh[1]) + (ssh[2] + ssh[3]);
        out[tid] = __fdividef(num, den);
    }
}

extern "C" void kernel_launch(void* const* d_in, const int* in_sizes, int n_in,
                              void* d_out, int out_size)
{
    const float* x          = (const float*)d_in[0];
    const float* hw         = (const float*)d_in[1];
    const float* hw_emb     = (const float*)d_in[2];
    const float* expert_emb = (const float*)d_in[3];
    float* out = (float*)d_out;

    mhn_kernel<<<1, 128>>>(x, hw, hw_emb, expert_emb, out);
}